// round 5
// baseline (speedup 1.0000x reference)
#include <cuda_runtime.h>
#include <cstdint>

// Problem constants: B=8192, T=2048, H=5, input dim 1.
#define MAX_B 8192
#define MAX_T 2048
#define HID 5

typedef unsigned long long ull;

// Packed x: xP[t/8][b][8] -> 32B per sequence per 8 steps, coalesced.
__device__ float g_xP[(size_t)MAX_T * MAX_B];

__device__ __forceinline__ float fast_tanh(float x) {
    float r;
    asm("tanh.approx.f32 %0, %1;" : "=f"(r) : "f"(x));
    return r;
}
__device__ __forceinline__ ull pk2(float lo, float hi) {
    ull r;
    asm("mov.b64 %0, {%1, %2};" : "=l"(r) : "f"(lo), "f"(hi));
    return r;
}
__device__ __forceinline__ void upk2(ull v, float& lo, float& hi) {
    asm("mov.b64 {%0, %1}, %2;" : "=f"(lo), "=f"(hi) : "l"(v));
}
// Packed fp32x2 FMA (sm_100+): one instruction = 2 fp32 FMAs.
__device__ __forceinline__ ull fma2(ull a, ull b, ull c) {
    ull r;
    asm("fma.rn.f32x2 %0, %1, %2, %3;" : "=l"(r) : "l"(a), "l"(b), "l"(c));
    return r;
}

// ---------------- pack: x[B,T] -> xP[T/8][B][8] ----------------
__global__ void pack_kernel(const float* __restrict__ x, int B, int T) {
    const int nblk = T / 8;
    int idx = blockIdx.x * blockDim.x + threadIdx.x;   // over B * nblk
    if (idx >= B * nblk) return;
    int b = idx / nblk;
    int k = idx - b * nblk;
    const float4* src = reinterpret_cast<const float4*>(x + (size_t)b * T + (size_t)k * 8);
    float4 u = src[0];
    float4 v = src[1];
    float4* dst = reinterpret_cast<float4*>(g_xP + ((size_t)k * B + b) * 8);
    dst[0] = u;
    dst[1] = v;
}

// ---------------- LSTM recurrence: FOUR lanes per sequence ----------------
// Lane q = tid&3 owns one gate row-block: q0=i, q1=g, q2=f, q3=o.
// Per step each lane computes its 5 gate pre-activations (z) and tanhs.
// Exchange per hidden unit j:
//   rA = shfl_xor(v,1): (i<->g),(f<->o);  p = v*rA  -> i*g on lanes q0,q1
//   rB = shfl_xor(v,2): q0<-f, q1<-o
//   rC = shfl_xor(rB,2^0... xor1 of rB): q0<-o, q1<-f
// Lanes q0,q1 compute the true c/h; lanes q2,q3 compute bounded garbage and
// receive the correct h via rD = shfl_xor(h,2). 1024 warps -> 2 per SMSP on
// 512 SMSPs: warp-level overlap hides the serial per-step chain.
__global__ void __launch_bounds__(256, 1) lstm_kernel(
    const float* __restrict__ W_ih,   // [20,1]
    const float* __restrict__ W_hh,   // [20,5]
    const float* __restrict__ b_ih,   // [20]
    const float* __restrict__ b_hh,   // [20]
    const float* __restrict__ W_fc,   // [1,5]
    const float* __restrict__ b_fc,   // [1]
    float* __restrict__ out,          // [B,1]
    int B, int T)
{
    const int tid = blockIdx.x * blockDim.x + threadIdx.x;  // 0..4B-1
    const int s   = tid >> 2;      // sequence id
    const int q   = tid & 3;       // gate type: 0=i, 1=g, 2=f, 3=o
    if (s >= B) return;

    const bool p1 = (q & 1) != 0;
    const bool p2 = (q & 2) != 0;

    // Row base per gate type (PyTorch order i,f,g,o): i->0, g->10, f->5, o->15
    const int base = (q == 0) ? 0 : (q == 1) ? 10 : (q == 2) ? 5 : 15;
    // sigmoid(z) = 0.5*tanh(z/2)+0.5 -> absorb 0.5 into weights for q!=1.
    const float sc = (q == 1) ? 1.0f : 0.5f;
    const float aq = sc;                       // post-tanh scale
    const float bq = (q == 1) ? 0.0f : 0.5f;   // post-tanh offset

    // Pack j-pairs (0,1),(2,3); j=4 scalar.
    ull wih01, wih23, b01, b23, whh01[HID], whh23[HID];
    float wih4, b4, whh4[HID];
    {
        float wr[HID], br[HID];
        #pragma unroll
        for (int j = 0; j < HID; j++) {
            wr[j] = W_ih[base + j] * sc;
            br[j] = (b_ih[base + j] + b_hh[base + j]) * sc;
        }
        wih01 = pk2(wr[0], wr[1]); wih23 = pk2(wr[2], wr[3]); wih4 = wr[4];
        b01 = pk2(br[0], br[1]); b23 = pk2(br[2], br[3]); b4 = br[4];
        #pragma unroll
        for (int k = 0; k < HID; k++) {
            whh01[k] = pk2(W_hh[(base + 0) * HID + k] * sc, W_hh[(base + 1) * HID + k] * sc);
            whh23[k] = pk2(W_hh[(base + 2) * HID + k] * sc, W_hh[(base + 3) * HID + k] * sc);
            whh4[k]  = W_hh[(base + 4) * HID + k] * sc;
        }
    }

    float h[HID], c[HID];
    #pragma unroll
    for (int j = 0; j < HID; j++) { h[j] = 0.0f; c[j] = 0.0f; }

    const int nblk = T / 8;
    const float4* xp0 = reinterpret_cast<const float4*>(g_xP);

    // prime first x block (4 lanes of a seq read the same 32B -> broadcast)
    float4 u = xp0[((size_t)0 * B + s) * 2 + 0];
    float4 v = xp0[((size_t)0 * B + s) * 2 + 1];

    for (int tb = 0; tb < nblk; tb++) {
        const int tn = (tb + 1 < nblk) ? (tb + 1) : tb;
        const float4 un = xp0[((size_t)tn * B + s) * 2 + 0];
        const float4 vn = xp0[((size_t)tn * B + s) * 2 + 1];

        const float xs[8] = {u.x, u.y, u.z, u.w, v.x, v.y, v.z, v.w};

        #pragma unroll
        for (int kk = 0; kk < 8; kk++) {
            const float xv = xs[kk];
            const ull x2 = pk2(xv, xv);

            // z for this lane's 5 gate rows
            ull z01 = fma2(x2, wih01, b01);
            ull z23 = fma2(x2, wih23, b23);
            float z4 = fmaf(xv, wih4, b4);
            #pragma unroll
            for (int k = 0; k < HID; k++) {
                const ull h2 = pk2(h[k], h[k]);
                z01 = fma2(h2, whh01[k], z01);
                z23 = fma2(h2, whh23[k], z23);
                z4 = fmaf(h[k], whh4[k], z4);
            }

            float za, zb, zc, zd;
            upk2(z01, za, zb);
            upk2(z23, zc, zd);

            float vv[HID];
            vv[0] = fmaf(aq, fast_tanh(za), bq);
            vv[1] = fmaf(aq, fast_tanh(zb), bq);
            vv[2] = fmaf(aq, fast_tanh(zc), bq);
            vv[3] = fmaf(aq, fast_tanh(zd), bq);
            vv[4] = fmaf(aq, fast_tanh(z4), bq);

            #pragma unroll
            for (int j = 0; j < HID; j++) {
                const float rA = __shfl_xor_sync(0xffffffffu, vv[j], 1);
                const float p  = vv[j] * rA;                    // i*g on q0,q1
                const float rB = __shfl_xor_sync(0xffffffffu, vv[j], 2);  // q0<-f, q1<-o
                const float rC = __shfl_xor_sync(0xffffffffu, rB, 1);     // q0<-o, q1<-f
                const float F = p1 ? rC : rB;
                const float O = p1 ? rB : rC;
                const float cn = fmaf(F, c[j], p);
                c[j] = cn;
                const float hn = O * fast_tanh(cn);             // true h on q0,q1
                const float rD = __shfl_xor_sync(0xffffffffu, hn, 2);
                h[j] = p2 ? rD : hn;                            // all lanes correct
            }
        }

        u = un; v = vn;
    }

    // relu(h) @ W_fc^T + b_fc  (lane q0 writes)
    if (q == 0) {
        float y = b_fc[0];
        #pragma unroll
        for (int j = 0; j < HID; j++) y = fmaf(fmaxf(h[j], 0.0f), W_fc[j], y);
        out[s] = y;
    }
}

extern "C" void kernel_launch(void* const* d_in, const int* in_sizes, int n_in,
                              void* d_out, int out_size) {
    const float* x    = (const float*)d_in[0];
    const float* W_ih = (const float*)d_in[1];
    const float* W_hh = (const float*)d_in[2];
    const float* b_ih = (const float*)d_in[3];
    const float* b_hh = (const float*)d_in[4];
    const float* W_fc = (const float*)d_in[5];
    const float* b_fc = (const float*)d_in[6];
    float* out = (float*)d_out;

    const int B = out_size;              // 8192
    const int T = in_sizes[0] / B;       // 2048

    const int npack = B * (T / 8);
    pack_kernel<<<(npack + 255) / 256, 256>>>(x, B, T);

    // 4 lanes/seq: 32768 threads = 128 blocks x 256 -> 8 warps/SM on 128 SMs
    // = 2 warps per SMSP on 512 SMSPs, single wave.
    const int threads = 256;
    const int blocks = (4 * B + threads - 1) / threads;  // 128
    lstm_kernel<<<blocks, threads>>>(W_ih, W_hh, b_ih, b_hh, W_fc, b_fc, out, B, T);
}

// round 6
// speedup vs baseline: 1.3438x; 1.3438x over previous
#include <cuda_runtime.h>
#include <cstdint>

// Problem constants: B=8192, T=2048, H=5, input dim 1.
#define MAX_B 8192
#define MAX_T 2048
#define HID 5

typedef unsigned long long ull;

// Packed x: xP[t/8][b][8] -> 32B per sequence per 8 steps, coalesced.
__device__ float g_xP[(size_t)MAX_T * MAX_B];

__device__ __forceinline__ float fast_tanh(float x) {
    float r;
    asm("tanh.approx.f32 %0, %1;" : "=f"(r) : "f"(x));
    return r;
}
__device__ __forceinline__ ull pk2(float lo, float hi) {
    ull r;
    asm("mov.b64 %0, {%1, %2};" : "=l"(r) : "f"(lo), "f"(hi));
    return r;
}
__device__ __forceinline__ void upk2(ull v, float& lo, float& hi) {
    asm("mov.b64 {%0, %1}, %2;" : "=f"(lo), "=f"(hi) : "l"(v));
}
// Packed fp32x2 FMA (sm_100+): one instruction = 2 fp32 FMAs.
__device__ __forceinline__ ull fma2(ull a, ull b, ull c) {
    ull r;
    asm("fma.rn.f32x2 %0, %1, %2, %3;" : "=l"(r) : "l"(a), "l"(b), "l"(c));
    return r;
}

// ---------------- pack: x[B,T] -> xP[T/8][B][8] ----------------
__global__ void pack_kernel(const float* __restrict__ x, int B, int T) {
    const int nblk = T / 8;
    int idx = blockIdx.x * blockDim.x + threadIdx.x;   // over B * nblk
    if (idx >= B * nblk) return;
    int b = idx / nblk;
    int k = idx - b * nblk;
    const float4* src = reinterpret_cast<const float4*>(x + (size_t)b * T + (size_t)k * 8);
    float4 u = src[0];
    float4 v = src[1];
    float4* dst = reinterpret_cast<float4*>(g_xP + ((size_t)k * B + b) * 8);
    dst[0] = u;
    dst[1] = v;
}

// ---------------- LSTM: 4 lanes/seq, ownership by hidden unit ----------------
// Lane q (= tid&3) owns unit q COMPLETELY (all 4 gate rows): its c/h update is
// lane-local, no shuffles. Unit 4's four gate rows are split one per lane by
// gate type (q0=i4, q1=g4, q2=f4, q3=o4) to balance z work at 5 rows/lane;
// unit 4's c/h is computed redundantly on all 4 lanes via a 4-shfl exchange.
// h0..h3 broadcast with 4 width-4 shuffles. 1024 warps -> 2/SMSP on 512 SMSPs.
__global__ void __launch_bounds__(256, 1) lstm_kernel(
    const float* __restrict__ W_ih,   // [20,1]
    const float* __restrict__ W_hh,   // [20,5]
    const float* __restrict__ b_ih,   // [20]
    const float* __restrict__ b_hh,   // [20]
    const float* __restrict__ W_fc,   // [1,5]
    const float* __restrict__ b_fc,   // [1]
    float* __restrict__ out,          // [B,1]
    int B, int T)
{
    const int tid = blockIdx.x * blockDim.x + threadIdx.x;  // 0..4B-1
    const int s   = tid >> 2;      // sequence id
    const int q   = tid & 3;       // lane role
    if (s >= B) return;

    // Own unit u = q. Rows (PyTorch order): i=u, f=5+u, g=10+u, o=15+u.
    // sigmoid(z) = 0.5*tanh(z/2)+0.5 -> fold 0.5 into i,f,o rows; g row x1.
    const int u = q;
    ull wif, wgo, bif, bgo, whhif[HID], whhgo[HID];
    {
        const int ri = u, rf = 5 + u, rg = 10 + u, ro = 15 + u;
        wif = pk2(W_ih[ri] * 0.5f, W_ih[rf] * 0.5f);
        wgo = pk2(W_ih[rg],        W_ih[ro] * 0.5f);
        bif = pk2((b_ih[ri] + b_hh[ri]) * 0.5f, (b_ih[rf] + b_hh[rf]) * 0.5f);
        bgo = pk2((b_ih[rg] + b_hh[rg]),        (b_ih[ro] + b_hh[ro]) * 0.5f);
        #pragma unroll
        for (int k = 0; k < HID; k++) {
            whhif[k] = pk2(W_hh[ri * HID + k] * 0.5f, W_hh[rf * HID + k] * 0.5f);
            whhgo[k] = pk2(W_hh[rg * HID + k],        W_hh[ro * HID + k] * 0.5f);
        }
    }

    // Unit-4 row by gate type: q0 -> i (row 4), q1 -> g (row 14),
    // q2 -> f (row 9), q3 -> o (row 19).
    const int r4 = (q == 0) ? 4 : (q == 1) ? 14 : (q == 2) ? 9 : 19;
    const float s4 = (q == 1) ? 1.0f : 0.5f;   // fold for sigmoid rows
    const float a4 = s4;
    const float o4b = (q == 1) ? 0.0f : 0.5f;
    float w4, b4, whh4[HID];
    w4 = W_ih[r4] * s4;
    b4 = (b_ih[r4] + b_hh[r4]) * s4;
    #pragma unroll
    for (int k = 0; k < HID; k++) whh4[k] = W_hh[r4 * HID + k] * s4;

    float h[HID];
    #pragma unroll
    for (int j = 0; j < HID; j++) h[j] = 0.0f;
    float cq = 0.0f, c4 = 0.0f;

    const bool selHi = (q & 2) != 0;

    const int nblk = T / 8;
    const float4* xp0 = reinterpret_cast<const float4*>(g_xP);

    // prime first x block (4 lanes of a seq read the same 32B -> broadcast)
    float4 xu = xp0[((size_t)0 * B + s) * 2 + 0];
    float4 xv = xp0[((size_t)0 * B + s) * 2 + 1];

    for (int tb = 0; tb < nblk; tb++) {
        const int tn = (tb + 1 < nblk) ? (tb + 1) : tb;
        const float4 un = xp0[((size_t)tn * B + s) * 2 + 0];
        const float4 vn = xp0[((size_t)tn * B + s) * 2 + 1];

        const float xs[8] = {xu.x, xu.y, xu.z, xu.w, xv.x, xv.y, xv.z, xv.w};

        #pragma unroll
        for (int kk = 0; kk < 8; kk++) {
            const float xval = xs[kk];
            const ull x2 = pk2(xval, xval);

            // 5 z rows: own-unit (i,f) and (g,o) packed, unit-4 row scalar.
            ull zif = fma2(x2, wif, bif);
            ull zgo = fma2(x2, wgo, bgo);
            float z4 = fmaf(xval, w4, b4);
            #pragma unroll
            for (int k = 0; k < HID; k++) {
                const ull h2 = pk2(h[k], h[k]);
                zif = fma2(h2, whhif[k], zif);
                zgo = fma2(h2, whhgo[k], zgo);
                z4 = fmaf(h[k], whh4[k], z4);
            }

            float zi, zf, zg, zo;
            upk2(zif, zi, zf);
            upk2(zgo, zg, zo);

            // own-unit gates + local c/h update (no shuffles!)
            const float ig = fmaf(0.5f, fast_tanh(zi), 0.5f);
            const float fg = fmaf(0.5f, fast_tanh(zf), 0.5f);
            const float gg = fast_tanh(zg);
            const float og = fmaf(0.5f, fast_tanh(zo), 0.5f);
            cq = fmaf(fg, cq, ig * gg);
            const float hq = og * fast_tanh(cq);

            // unit-4 gate value on this lane
            const float v4 = fmaf(a4, fast_tanh(z4), o4b);

            // unit-4 exchange: v4 layout q0=i4,q1=g4,q2=f4,q3=o4
            const float rA = __shfl_xor_sync(0xffffffffu, v4, 1);
            const float p  = v4 * rA;                              // i4*g4 on q0,q1
            const float px = __shfl_xor_sync(0xffffffffu, p, 2);   // i4*g4 -> q2,q3
            const float P  = selHi ? px : p;                       // i4*g4 everywhere
            const float rB = __shfl_xor_sync(0xffffffffu, v4, 2);
            const float rC = __shfl_xor_sync(0xffffffffu, rB, 1);
            // F4: q0<-rB, q1<-rC, q2<-v4, q3<-rA ; O4: q0<-rC, q1<-rB, q2<-rA, q3<-v4
            const float F4 = selHi ? ((q & 1) ? rA : v4) : ((q & 1) ? rC : rB);
            const float O4 = selHi ? ((q & 1) ? v4 : rA) : ((q & 1) ? rB : rC);
            c4 = fmaf(F4, c4, P);                                  // identical on all lanes
            const float h4 = O4 * fast_tanh(c4);

            // broadcast own-unit h within the 4-lane group
            h[0] = __shfl_sync(0xffffffffu, hq, 0, 4);
            h[1] = __shfl_sync(0xffffffffu, hq, 1, 4);
            h[2] = __shfl_sync(0xffffffffu, hq, 2, 4);
            h[3] = __shfl_sync(0xffffffffu, hq, 3, 4);
            h[4] = h4;
        }

        xu = un; xv = vn;
    }

    // relu(h) @ W_fc^T + b_fc  (lane q0 writes; it has all h values)
    if (q == 0) {
        float y = b_fc[0];
        #pragma unroll
        for (int j = 0; j < HID; j++) y = fmaf(fmaxf(h[j], 0.0f), W_fc[j], y);
        out[s] = y;
    }
}

extern "C" void kernel_launch(void* const* d_in, const int* in_sizes, int n_in,
                              void* d_out, int out_size) {
    const float* x    = (const float*)d_in[0];
    const float* W_ih = (const float*)d_in[1];
    const float* W_hh = (const float*)d_in[2];
    const float* b_ih = (const float*)d_in[3];
    const float* b_hh = (const float*)d_in[4];
    const float* W_fc = (const float*)d_in[5];
    const float* b_fc = (const float*)d_in[6];
    float* out = (float*)d_out;

    const int B = out_size;              // 8192
    const int T = in_sizes[0] / B;       // 2048

    const int npack = B * (T / 8);
    pack_kernel<<<(npack + 255) / 256, 256>>>(x, B, T);

    // 4 lanes/seq: 32768 threads = 128 blocks x 256 -> 8 warps/SM on 128 SMs
    // = 2 warps per SMSP on 512 SMSPs, single wave.
    const int threads = 256;
    const int blocks = (4 * B + threads - 1) / threads;  // 128
    lstm_kernel<<<blocks, threads>>>(W_ih, W_hh, b_ih, b_hh, W_fc, b_fc, out, B, T);
}